// round 2
// baseline (speedup 1.0000x reference)
#include <cuda_runtime.h>
#include <cuda_bf16.h>
#include <cstdint>

// Problem constants
#define BB 32
#define SS 512
#define EE 300
#define EP 304          // padded K
#define HH 128
#define G4 512          // 4*H
#define NN 1024         // fused fwd+bwd gate width

// Scratch (device globals; allocation-free rule)
__device__ float g_X[(size_t)BB * SS * EP];        // padded embeddings [16384][304]
__device__ float g_W[(size_t)EP * NN];             // packed input weights W[k][n]
__device__ float g_bias[NN];
__device__ float g_G[(size_t)BB * SS * NN];        // gate preactivations [16384][1024]
__device__ float g_pooled[BB * 2 * HH];            // [b][dir*128+idx]

// ---------- f32x2 helpers ----------
__device__ __forceinline__ unsigned long long fma2(unsigned long long a,
                                                   unsigned long long b,
                                                   unsigned long long c) {
    unsigned long long d;
    asm("fma.rn.f32x2 %0, %1, %2, %3;" : "=l"(d) : "l"(a), "l"(b), "l"(c));
    return d;
}
__device__ __forceinline__ unsigned long long bcast2(float x) {
    unsigned long long d;
    asm("mov.b64 %0, {%1, %1};" : "=l"(d) : "f"(x));
    return d;
}
__device__ __forceinline__ float2 unpk(unsigned long long v) {
    float2 r;
    asm("mov.b64 {%0, %1}, %2;" : "=f"(r.x), "=f"(r.y) : "l"(v));
    return r;
}

__device__ __forceinline__ float fsigmoid(float x) {
    return 1.0f / (1.0f + __expf(-x));
}
__device__ __forceinline__ float ftanh(float x) {
    float ax = fabsf(x);
    float e = __expf(2.0f * ax);
    float t = 1.0f - 2.0f / (e + 1.0f);
    return copysignf(t, x);
}

// ---------- Kernel 1: pack input-projection weights + bias ----------
__global__ void pack_w_kernel(const float* __restrict__ Wih_f,
                              const float* __restrict__ Wih_b,
                              const float* __restrict__ b_f,
                              const float* __restrict__ b_b) {
    int idx = blockIdx.x * 256 + threadIdx.x;
    if (idx < EP * NN) {
        int k = idx >> 10;
        int n = idx & 1023;
        float v = 0.0f;
        if (k < EE) v = (n < G4) ? Wih_f[n * EE + k] : Wih_b[(n - G4) * EE + k];
        g_W[idx] = v;
    }
    if (idx < NN) g_bias[idx] = (idx < G4) ? b_f[idx] : b_b[idx - G4];
}

// ---------- Kernel 2: embeddings with dep-mean blend ----------
__global__ void embed_kernel(const int* __restrict__ word_ids,
                             const int* __restrict__ deps_ids,
                             const float* __restrict__ word_table,
                             const float* __restrict__ dep_table) {
    int bs = blockIdx.x;           // 0..16383
    int b = bs >> 9;
    int s = bs & 511;
    int wid = word_ids[b * (3 * SS) + SS + s];

    int ids[8];
    float cnt = 0.0f;
#pragma unroll
    for (int d = 0; d < 8; d++) {
        ids[d] = deps_ids[bs * 8 + d];
        if (ids[d] > 1) cnt += 1.0f;   // PAD=0, UNK=1
    }
    float inv = (cnt > 0.0f) ? 0.5f / cnt : 0.0f;
    float wscale = (cnt > 0.0f) ? 0.5f : 1.0f;

    for (int e = threadIdx.x; e < EP; e += 128) {
        float v = 0.0f;
        if (e < EE) {
            float w = word_table[(size_t)wid * EE + e];
            float sum = 0.0f;
#pragma unroll
            for (int d = 0; d < 8; d++) {
                if (ids[d] > 1) sum += dep_table[ids[d] * EE + e];
            }
            v = wscale * w + inv * sum;
        }
        g_X[(size_t)bs * EP + e] = v;
    }
}

// ---------- Kernel 3: GEMM G = X @ W + bias (M=16384, N=1024, K=304) ----------
__global__ void __launch_bounds__(256) gemm_kernel() {
    __shared__ float As[16][132];   // transposed A tile, padded
    __shared__ float Bs[16][64];

    int tid = threadIdx.x;
    int bm = blockIdx.x * 128;
    int bn = blockIdx.y * 64;
    int ty = tid >> 4, tx = tid & 15;     // compute layout: rows ty*8..+8, cols tx*4..+4
    int ar = tid >> 2, ac = (tid & 3) << 2;  // load layout

    unsigned long long acc[4][4];
#pragma unroll
    for (int q = 0; q < 4; q++)
#pragma unroll
        for (int n = 0; n < 4; n++) acc[q][n] = 0ull;

    for (int k0 = 0; k0 < EP; k0 += 16) {
#pragma unroll
        for (int rr = 0; rr < 2; rr++) {
            float4 a = *(const float4*)(g_X + (size_t)(bm + ar + rr * 64) * EP + k0 + ac);
            As[ac + 0][ar + rr * 64] = a.x;
            As[ac + 1][ar + rr * 64] = a.y;
            As[ac + 2][ar + rr * 64] = a.z;
            As[ac + 3][ar + rr * 64] = a.w;
        }
        *(float4*)&Bs[ty][tx * 4] =
            *(const float4*)(g_W + (size_t)(k0 + ty) * NN + bn + tx * 4);
        __syncthreads();

#pragma unroll
        for (int kk = 0; kk < 16; kk++) {
            const unsigned long long* ap = (const unsigned long long*)&As[kk][ty * 8];
            unsigned long long a0 = ap[0], a1 = ap[1], a2 = ap[2], a3 = ap[3];
            float4 bq = *(const float4*)&Bs[kk][tx * 4];
            unsigned long long b0 = bcast2(bq.x), b1 = bcast2(bq.y),
                               b2 = bcast2(bq.z), b3 = bcast2(bq.w);
            acc[0][0] = fma2(a0, b0, acc[0][0]); acc[0][1] = fma2(a0, b1, acc[0][1]);
            acc[0][2] = fma2(a0, b2, acc[0][2]); acc[0][3] = fma2(a0, b3, acc[0][3]);
            acc[1][0] = fma2(a1, b0, acc[1][0]); acc[1][1] = fma2(a1, b1, acc[1][1]);
            acc[1][2] = fma2(a1, b2, acc[1][2]); acc[1][3] = fma2(a1, b3, acc[1][3]);
            acc[2][0] = fma2(a2, b0, acc[2][0]); acc[2][1] = fma2(a2, b1, acc[2][1]);
            acc[2][2] = fma2(a2, b2, acc[2][2]); acc[2][3] = fma2(a2, b3, acc[2][3]);
            acc[3][0] = fma2(a3, b0, acc[3][0]); acc[3][1] = fma2(a3, b1, acc[3][1]);
            acc[3][2] = fma2(a3, b2, acc[3][2]); acc[3][3] = fma2(a3, b3, acc[3][3]);
        }
        __syncthreads();
    }

    float bb0 = g_bias[bn + tx * 4 + 0];
    float bb1 = g_bias[bn + tx * 4 + 1];
    float bb2 = g_bias[bn + tx * 4 + 2];
    float bb3 = g_bias[bn + tx * 4 + 3];
#pragma unroll
    for (int q = 0; q < 4; q++) {
        float2 v0 = unpk(acc[q][0]), v1 = unpk(acc[q][1]);
        float2 v2 = unpk(acc[q][2]), v3 = unpk(acc[q][3]);
        int row0 = bm + ty * 8 + q * 2;
        *(float4*)(g_G + (size_t)row0 * NN + bn + tx * 4) =
            make_float4(v0.x + bb0, v1.x + bb1, v2.x + bb2, v3.x + bb3);
        *(float4*)(g_G + (size_t)(row0 + 1) * NN + bn + tx * 4) =
            make_float4(v0.y + bb0, v1.y + bb1, v2.y + bb2, v3.y + bb3);
    }
}

// ---------- Kernel 4: LSTM scan (one CTA per (batch, dir)) ----------
// Layout: warp w, lane l. gi = l&3 (gate), hu = w*8 + (l>>2) (hidden unit).
// Thread owns gate row r = gi*128+hu. All 4 gates of a hidden unit live in
// one 4-lane group -> gate exchange via shfl (no block barrier).
// Double-buffered h in smem -> ONE __syncthreads per step.
// gpre prefetched one timestep ahead to hide DRAM latency.
#define SCAN_SMEM (1024 + 16 * 512 * 8)

__global__ void __launch_bounds__(512, 1)
lstm_scan_kernel(const float* __restrict__ Whh_f, const float* __restrict__ Whh_b) {
    extern __shared__ unsigned char sm[];
    float* hbuf = (float*)sm;                                   // [2][128]
    unsigned long long* wsp = (unsigned long long*)(sm + 1024); // [16][512]

    int tid = threadIdx.x;
    int l = tid & 31;
    int w = tid >> 5;
    int gi = l & 3;
    int hu = w * 8 + (l >> 2);
    int r = gi * HH + hu;          // gate row this thread owns
    int b = blockIdx.x;
    int dir = blockIdx.y;
    const float* Whh = dir ? Whh_b : Whh_f;

    const unsigned long long* wrow = (const unsigned long long*)(Whh + r * HH);
    unsigned long long wreg[48];
#pragma unroll
    for (int m = 0; m < 48; m++) wreg[m] = wrow[m];
#pragma unroll
    for (int m = 0; m < 16; m++) wsp[m * 512 + tid] = wrow[48 + m];

    if (tid < 256) hbuf[tid] = 0.0f;   // both buffers
    float c = 0.0f, hmax = -1e30f;

    const float* gp = dir ? (g_G + ((size_t)(b * SS + SS - 1)) * NN + G4 + r)
                          : (g_G + ((size_t)(b * SS)) * NN + r);
    long stepoff = dir ? -(long)NN : (long)NN;

    float gpre = __ldg(gp);
    gp += stepoff;
    __syncthreads();

    int p = 0;
    for (int t = 0; t < SS; t++) {
        // prefetch next step's gate preactivation (hides DRAM latency)
        float gnext = 0.0f;
        if (t + 1 < SS) gnext = __ldg(gp);
        gp += stepoff;

        const ulonglong2* hq = (const ulonglong2*)(hbuf + p * HH);
        unsigned long long a0 = 0ull, a1 = 0ull, a2 = 0ull, a3 = 0ull;
#pragma unroll
        for (int m = 0; m < 12; m++) {
            ulonglong2 q0 = hq[2 * m], q1 = hq[2 * m + 1];
            a0 = fma2(wreg[4 * m + 0], q0.x, a0);
            a1 = fma2(wreg[4 * m + 1], q0.y, a1);
            a2 = fma2(wreg[4 * m + 2], q1.x, a2);
            a3 = fma2(wreg[4 * m + 3], q1.y, a3);
        }
#pragma unroll
        for (int m = 0; m < 4; m++) {
            ulonglong2 q0 = hq[24 + 2 * m], q1 = hq[24 + 2 * m + 1];
            a0 = fma2(wsp[(4 * m + 0) * 512 + tid], q0.x, a0);
            a1 = fma2(wsp[(4 * m + 1) * 512 + tid], q0.y, a1);
            a2 = fma2(wsp[(4 * m + 2) * 512 + tid], q1.x, a2);
            a3 = fma2(wsp[(4 * m + 3) * 512 + tid], q1.y, a3);
        }
        float2 s0 = unpk(a0), s1 = unpk(a1), s2 = unpk(a2), s3 = unpk(a3);
        float sum = gpre + ((s0.x + s0.y) + (s1.x + s1.y))
                         + ((s2.x + s2.y) + (s3.x + s3.y));

        // gather this hidden unit's 4 gate preactivations via shfl
        int base = l & ~3;
        float pi = __shfl_sync(0xffffffffu, sum, base + 0);
        float pf = __shfl_sync(0xffffffffu, sum, base + 1);
        float pg = __shfl_sync(0xffffffffu, sum, base + 2);
        float po = __shfl_sync(0xffffffffu, sum, base + 3);

        // all 4 lanes of the group compute identical c/h (no divergence)
        c = fsigmoid(pf) * c + fsigmoid(pi) * ftanh(pg);
        float hh = fsigmoid(po) * ftanh(c);
        hmax = fmaxf(hmax, hh);

        if (gi == 0) hbuf[(p ^ 1) * HH + hu] = hh;
        __syncthreads();
        p ^= 1;
        gpre = gnext;
    }

    if (gi == 0) g_pooled[b * 256 + dir * HH + hu] = hmax;
}

// ---------- Kernel 5: classifier ----------
__global__ void cls_kernel(const float* __restrict__ W_cls,
                           const float* __restrict__ b_cls,
                           float* __restrict__ out) {
    int t = threadIdx.x;
    if (t >= BB * 5) return;
    int b = t / 5, l = t % 5;
    float s = b_cls[l];
#pragma unroll 8
    for (int k = 0; k < 256; k++) s += g_pooled[b * 256 + k] * W_cls[l * 256 + k];
    out[b * 5 + l] = s;
}

// ---------- launch ----------
extern "C" void kernel_launch(void* const* d_in, const int* in_sizes, int n_in,
                              void* d_out, int out_size) {
    const int*   word_ids   = (const int*)d_in[0];
    const int*   deps_ids   = (const int*)d_in[1];
    const float* word_table = (const float*)d_in[2];
    const float* dep_table  = (const float*)d_in[3];
    const float* Wih_f      = (const float*)d_in[4];
    const float* Whh_f      = (const float*)d_in[5];
    const float* b_f        = (const float*)d_in[6];
    const float* Wih_b      = (const float*)d_in[7];
    const float* Whh_b      = (const float*)d_in[8];
    const float* b_b        = (const float*)d_in[9];
    const float* W_cls      = (const float*)d_in[10];
    const float* b_cls      = (const float*)d_in[11];
    float* out = (float*)d_out;

    cudaFuncSetAttribute(lstm_scan_kernel,
                         cudaFuncAttributeMaxDynamicSharedMemorySize, SCAN_SMEM);

    pack_w_kernel<<<(EP * NN + 255) / 256, 256>>>(Wih_f, Wih_b, b_f, b_b);
    embed_kernel<<<BB * SS, 128>>>(word_ids, deps_ids, word_table, dep_table);
    gemm_kernel<<<dim3((BB * SS) / 128, NN / 64), 256>>>();
    lstm_scan_kernel<<<dim3(BB, 2), 512, SCAN_SMEM>>>(Whh_f, Whh_b);
    cls_kernel<<<1, 256>>>(W_cls, b_cls, out);
}

// round 3
// speedup vs baseline: 1.4113x; 1.4113x over previous
#include <cuda_runtime.h>
#include <cuda_bf16.h>
#include <cstdint>

// Problem constants
#define BB 32
#define SS 512
#define EE 300
#define EP 304          // padded K
#define HH 128
#define G4 512          // 4*H
#define NN 1024         // fused fwd+bwd gate width

// Scratch (device globals; allocation-free rule)
__device__ float g_X[(size_t)BB * SS * EP];        // padded embeddings [16384][304]
__device__ float g_W[(size_t)EP * NN];             // packed input weights W[k][n]
__device__ float g_bias[NN];
__device__ float g_G[(size_t)BB * SS * NN];        // gate preactivations [16384][1024]
__device__ float g_pooled[BB * 2 * HH];            // [b][dir*128+idx]

// ---------- f32x2 helpers ----------
__device__ __forceinline__ unsigned long long fma2(unsigned long long a,
                                                   unsigned long long b,
                                                   unsigned long long c) {
    unsigned long long d;
    asm("fma.rn.f32x2 %0, %1, %2, %3;" : "=l"(d) : "l"(a), "l"(b), "l"(c));
    return d;
}
__device__ __forceinline__ unsigned long long bcast2(float x) {
    unsigned long long d;
    asm("mov.b64 %0, {%1, %1};" : "=l"(d) : "f"(x));
    return d;
}
__device__ __forceinline__ float2 unpk(unsigned long long v) {
    float2 r;
    asm("mov.b64 {%0, %1}, %2;" : "=f"(r.x), "=f"(r.y) : "l"(v));
    return r;
}
__device__ __forceinline__ float tanh_ap(float x) {
    float y;
    asm("tanh.approx.f32 %0, %1;" : "=f"(y) : "f"(x));
    return y;
}
// accurate tanh via ex2 (for the recurrent cell state path)
__device__ __forceinline__ float ftanh(float x) {
    float ax = fabsf(x);
    float e = __expf(2.0f * ax);
    float t = 1.0f - 2.0f / (e + 1.0f);
    return copysignf(t, x);
}
__device__ __forceinline__ unsigned int smem_u32(const void* p) {
    unsigned int a;
    asm("{ .reg .u64 t; cvta.to.shared.u64 t, %1; cvt.u32.u64 %0, t; }"
        : "=r"(a) : "l"(p));
    return a;
}

// ---------- Kernel 1: pack input-projection weights + bias ----------
__global__ void pack_w_kernel(const float* __restrict__ Wih_f,
                              const float* __restrict__ Wih_b,
                              const float* __restrict__ b_f,
                              const float* __restrict__ b_b) {
    int idx = blockIdx.x * 256 + threadIdx.x;
    if (idx < EP * NN) {
        int k = idx >> 10;
        int n = idx & 1023;
        float v = 0.0f;
        if (k < EE) v = (n < G4) ? Wih_f[n * EE + k] : Wih_b[(n - G4) * EE + k];
        g_W[idx] = v;
    }
    if (idx < NN) g_bias[idx] = (idx < G4) ? b_f[idx] : b_b[idx - G4];
}

// ---------- Kernel 2: embeddings with dep-mean blend ----------
__global__ void embed_kernel(const int* __restrict__ word_ids,
                             const int* __restrict__ deps_ids,
                             const float* __restrict__ word_table,
                             const float* __restrict__ dep_table) {
    int bs = blockIdx.x;           // 0..16383
    int b = bs >> 9;
    int s = bs & 511;
    int wid = word_ids[b * (3 * SS) + SS + s];

    int ids[8];
    float cnt = 0.0f;
#pragma unroll
    for (int d = 0; d < 8; d++) {
        ids[d] = deps_ids[bs * 8 + d];
        if (ids[d] > 1) cnt += 1.0f;   // PAD=0, UNK=1
    }
    float inv = (cnt > 0.0f) ? 0.5f / cnt : 0.0f;
    float wscale = (cnt > 0.0f) ? 0.5f : 1.0f;

    for (int e = threadIdx.x; e < EP; e += 128) {
        float v = 0.0f;
        if (e < EE) {
            float w = word_table[(size_t)wid * EE + e];
            float sum = 0.0f;
#pragma unroll
            for (int d = 0; d < 8; d++) {
                if (ids[d] > 1) sum += dep_table[ids[d] * EE + e];
            }
            v = wscale * w + inv * sum;
        }
        g_X[(size_t)bs * EP + e] = v;
    }
}

// ---------- Kernel 3: GEMM G = X @ W + bias (M=16384, N=1024, K=304) ----------
__global__ void __launch_bounds__(256) gemm_kernel() {
    __shared__ float As[16][132];   // transposed A tile, padded
    __shared__ float Bs[16][64];

    int tid = threadIdx.x;
    int bm = blockIdx.x * 128;
    int bn = blockIdx.y * 64;
    int ty = tid >> 4, tx = tid & 15;
    int ar = tid >> 2, ac = (tid & 3) << 2;

    unsigned long long acc[4][4];
#pragma unroll
    for (int q = 0; q < 4; q++)
#pragma unroll
        for (int n = 0; n < 4; n++) acc[q][n] = 0ull;

    for (int k0 = 0; k0 < EP; k0 += 16) {
#pragma unroll
        for (int rr = 0; rr < 2; rr++) {
            float4 a = *(const float4*)(g_X + (size_t)(bm + ar + rr * 64) * EP + k0 + ac);
            As[ac + 0][ar + rr * 64] = a.x;
            As[ac + 1][ar + rr * 64] = a.y;
            As[ac + 2][ar + rr * 64] = a.z;
            As[ac + 3][ar + rr * 64] = a.w;
        }
        *(float4*)&Bs[ty][tx * 4] =
            *(const float4*)(g_W + (size_t)(k0 + ty) * NN + bn + tx * 4);
        __syncthreads();

#pragma unroll
        for (int kk = 0; kk < 16; kk++) {
            const unsigned long long* ap = (const unsigned long long*)&As[kk][ty * 8];
            unsigned long long a0 = ap[0], a1 = ap[1], a2 = ap[2], a3 = ap[3];
            float4 bq = *(const float4*)&Bs[kk][tx * 4];
            unsigned long long b0 = bcast2(bq.x), b1 = bcast2(bq.y),
                               b2 = bcast2(bq.z), b3 = bcast2(bq.w);
            acc[0][0] = fma2(a0, b0, acc[0][0]); acc[0][1] = fma2(a0, b1, acc[0][1]);
            acc[0][2] = fma2(a0, b2, acc[0][2]); acc[0][3] = fma2(a0, b3, acc[0][3]);
            acc[1][0] = fma2(a1, b0, acc[1][0]); acc[1][1] = fma2(a1, b1, acc[1][1]);
            acc[1][2] = fma2(a1, b2, acc[1][2]); acc[1][3] = fma2(a1, b3, acc[1][3]);
            acc[2][0] = fma2(a2, b0, acc[2][0]); acc[2][1] = fma2(a2, b1, acc[2][1]);
            acc[2][2] = fma2(a2, b2, acc[2][2]); acc[2][3] = fma2(a2, b3, acc[2][3]);
            acc[3][0] = fma2(a3, b0, acc[3][0]); acc[3][1] = fma2(a3, b1, acc[3][1]);
            acc[3][2] = fma2(a3, b2, acc[3][2]); acc[3][3] = fma2(a3, b3, acc[3][3]);
        }
        __syncthreads();
    }

    float bb0 = g_bias[bn + tx * 4 + 0];
    float bb1 = g_bias[bn + tx * 4 + 1];
    float bb2 = g_bias[bn + tx * 4 + 2];
    float bb3 = g_bias[bn + tx * 4 + 3];
#pragma unroll
    for (int q = 0; q < 4; q++) {
        float2 v0 = unpk(acc[q][0]), v1 = unpk(acc[q][1]);
        float2 v2 = unpk(acc[q][2]), v3 = unpk(acc[q][3]);
        int row0 = bm + ty * 8 + q * 2;
        *(float4*)(g_G + (size_t)row0 * NN + bn + tx * 4) =
            make_float4(v0.x + bb0, v1.x + bb1, v2.x + bb2, v3.x + bb3);
        *(float4*)(g_G + (size_t)(row0 + 1) * NN + bn + tx * 4) =
            make_float4(v0.y + bb0, v1.y + bb1, v2.y + bb2, v3.y + bb3);
    }
}

// ---------- Kernel 4: LSTM scan — 2-CTA cluster per (batch,dir) chain ----------
// CTA rank r owns hidden units [r*64, r*64+64) (all 4 gates = 256 rows).
// 512 threads: lane l -> khalf=l&1 (K half), gi=(l>>1)&3 (gate), hg=l>>3.
// hu = rank*64 + warp*4 + hg. Each thread: 64 reg-resident weights (32 f32x2).
// Per step: dot halves -> shfl_xor reduce -> one tanh.approx covers all gates
// -> shfl gather -> c/h update -> h pushed to peer via st.async + mbarrier tx.
__global__ void __launch_bounds__(512, 1) __cluster_dims__(2, 1, 1)
lstm_scan_kernel(const float* __restrict__ Whh_f, const float* __restrict__ Whh_b) {
    __shared__ float hbuf[2 * HH];
    __shared__ __align__(8) unsigned long long bars[2];

    int tid = threadIdx.x;
    int l = tid & 31;
    int w = tid >> 5;
    int khalf = l & 1;
    int gi = (l >> 1) & 3;
    int hg = l >> 3;

    unsigned int rank;
    asm("mov.u32 %0, %%cluster_ctarank;" : "=r"(rank));
    unsigned int peer = rank ^ 1u;

    int hu = rank * 64 + w * 4 + hg;       // hidden unit this 8-lane group owns
    int row = gi * HH + hu;                // gate row
    int b = blockIdx.x >> 1;               // cluster id on x
    int dir = blockIdx.y;
    const float* Whh = dir ? Whh_b : Whh_f;

    // 64 register-resident weights (32 f32x2)
    const unsigned long long* wrow =
        (const unsigned long long*)(Whh + (size_t)row * HH + khalf * 64);
    unsigned long long wreg[32];
#pragma unroll
    for (int m = 0; m < 32; m++) wreg[m] = wrow[m];

    // init smem
    if (tid < 2 * HH) hbuf[tid] = 0.0f;
    if (tid == 0) {
        unsigned int b0 = smem_u32(&bars[0]);
        asm volatile("mbarrier.init.shared.b64 [%0], 1;" :: "r"(b0) : "memory");
        asm volatile("mbarrier.init.shared.b64 [%0], 1;" :: "r"(b0 + 8) : "memory");
    }
    __syncthreads();
    // cluster barrier: mbarriers + zeroed hbuf visible before any peer st.async
    asm volatile("barrier.cluster.arrive.aligned;" ::: "memory");
    asm volatile("barrier.cluster.wait.aligned;" ::: "memory");

    // remote (peer) addresses
    unsigned int hb_l = smem_u32(hbuf);
    unsigned int bar_l = smem_u32(&bars[0]);
    unsigned int hb_r, bar_r;
    asm("mapa.shared::cluster.u32 %0, %1, %2;" : "=r"(hb_r) : "r"(hb_l), "r"(peer));
    asm("mapa.shared::cluster.u32 %0, %1, %2;" : "=r"(bar_r) : "r"(bar_l), "r"(peer));

    float c = 0.0f, hmax = -1e30f;

    const float* gp = dir ? (g_G + ((size_t)(b * SS + SS - 1)) * NN + G4 + row)
                          : (g_G + ((size_t)(b * SS)) * NN + row);
    long stepoff = dir ? -(long)NN : (long)NN;

    float gpre = khalf ? 0.0f : __ldg(gp);
    gp += stepoff;

    int p = 0;
    for (int t = 0; t < SS; t++) {
        // prefetch next step's gate preactivation (khalf==0 lanes only)
        float gnext = 0.0f;
        if (!khalf && t + 1 < SS) gnext = __ldg(gp);
        gp += stepoff;

        // dot over this thread's K-half of h
        const ulonglong2* hq = (const ulonglong2*)(hbuf + p * HH + khalf * 64);
        unsigned long long a0 = 0ull, a1 = 0ull, a2 = 0ull, a3 = 0ull;
#pragma unroll
        for (int m = 0; m < 8; m++) {
            ulonglong2 q0 = hq[2 * m], q1 = hq[2 * m + 1];
            a0 = fma2(wreg[4 * m + 0], q0.x, a0);
            a1 = fma2(wreg[4 * m + 1], q0.y, a1);
            a2 = fma2(wreg[4 * m + 2], q1.x, a2);
            a3 = fma2(wreg[4 * m + 3], q1.y, a3);
        }
        float2 s0 = unpk(a0), s1 = unpk(a1), s2 = unpk(a2), s3 = unpk(a3);
        float s = ((s0.x + s0.y) + (s1.x + s1.y)) + ((s2.x + s2.y) + (s3.x + s3.y));
        // combine two K-halves
        s += __shfl_xor_sync(0xffffffffu, s, 1);
        if (!khalf) s += gpre;

        // one tanh.approx per warp covers all gates (sigmoid = 0.5+0.5*tanh(x/2))
        float targ = (gi == 2) ? s : 0.5f * s;
        float tv = tanh_ap(targ);

        int base = l & ~7;
        float ti = __shfl_sync(0xffffffffu, tv, base + 0);
        float tf = __shfl_sync(0xffffffffu, tv, base + 2);
        float tg = __shfl_sync(0xffffffffu, tv, base + 4);
        float to = __shfl_sync(0xffffffffu, tv, base + 6);

        float ig = fmaf(0.5f, ti, 0.5f);
        float fg = fmaf(0.5f, tf, 0.5f);
        float og = fmaf(0.5f, to, 0.5f);
        c = fg * c + ig * tg;
        float hh = og * ftanh(c);      // accurate tanh on the state path
        hmax = fmaxf(hmax, hh);

        int pn = p ^ 1;
        if ((l & 7) == 0) {
            hbuf[pn * HH + hu] = hh;   // local copy
            // push to peer's hbuf, complete_tx on peer's bar[t&1]
            unsigned int raddr = hb_r + (unsigned)((pn * HH + hu) * 4);
            unsigned int rmbar = bar_r + (unsigned)((t & 1) * 8);
            asm volatile(
                "st.async.shared::cluster.mbarrier::complete_tx::bytes.f32 [%0], %1, [%2];"
                :: "r"(raddr), "f"(hh), "r"(rmbar) : "memory");
        }
        __syncthreads();
        if (tid == 0) {
            // arrive (count=1) + expect 64*4 bytes from peer this phase
            asm volatile(
                "mbarrier.arrive.expect_tx.shared.b64 _, [%0], 256;"
                :: "r"(bar_l + (unsigned)((t & 1) * 8)) : "memory");
        }
        // wait: bar[t&1], phase parity flips once per two steps
        {
            unsigned int mb = bar_l + (unsigned)((t & 1) * 8);
            unsigned int par = (t >> 1) & 1;
            unsigned int done;
            asm volatile(
                "{\n\t.reg .pred P;\n\t"
                "mbarrier.try_wait.parity.acquire.cta.shared::cta.b64 P, [%1], %2;\n\t"
                "selp.b32 %0, 1, 0, P;\n\t}"
                : "=r"(done) : "r"(mb), "r"(par) : "memory");
            if (!done) {
                asm volatile(
                    "{\n\t.reg .pred P;\n"
                    "WL%=:\n\t"
                    "mbarrier.try_wait.parity.acquire.cta.shared::cta.b64 P, [%0], %1, 0x989680;\n\t"
                    "@P bra.uni WD%=;\n\t"
                    "bra.uni WL%=;\n"
                    "WD%=:\n\t}"
                    :: "r"(mb), "r"(par) : "memory");
            }
        }
        p = pn;
        gpre = gnext;
    }

    if ((l & 7) == 0) g_pooled[b * 256 + dir * HH + hu] = hmax;

    // keep cluster alive until both CTAs are done (peer may still push)
    asm volatile("barrier.cluster.arrive.aligned;" ::: "memory");
    asm volatile("barrier.cluster.wait.aligned;" ::: "memory");
}

// ---------- Kernel 5: classifier ----------
__global__ void cls_kernel(const float* __restrict__ W_cls,
                           const float* __restrict__ b_cls,
                           float* __restrict__ out) {
    int t = threadIdx.x;
    if (t >= BB * 5) return;
    int b = t / 5, l = t % 5;
    float s = b_cls[l];
#pragma unroll 8
    for (int k = 0; k < 256; k++) s += g_pooled[b * 256 + k] * W_cls[l * 256 + k];
    out[b * 5 + l] = s;
}

// ---------- launch ----------
extern "C" void kernel_launch(void* const* d_in, const int* in_sizes, int n_in,
                              void* d_out, int out_size) {
    const int*   word_ids   = (const int*)d_in[0];
    const int*   deps_ids   = (const int*)d_in[1];
    const float* word_table = (const float*)d_in[2];
    const float* dep_table  = (const float*)d_in[3];
    const float* Wih_f      = (const float*)d_in[4];
    const float* Whh_f      = (const float*)d_in[5];
    const float* b_f        = (const float*)d_in[6];
    const float* Wih_b      = (const float*)d_in[7];
    const float* Whh_b      = (const float*)d_in[8];
    const float* b_b        = (const float*)d_in[9];
    const float* W_cls      = (const float*)d_in[10];
    const float* b_cls      = (const float*)d_in[11];
    float* out = (float*)d_out;

    pack_w_kernel<<<(EP * NN + 255) / 256, 256>>>(Wih_f, Wih_b, b_f, b_b);
    embed_kernel<<<BB * SS, 128>>>(word_ids, deps_ids, word_table, dep_table);
    gemm_kernel<<<dim3((BB * SS) / 128, NN / 64), 256>>>();
    // grid.x = 64 (32 chains * 2 cluster CTAs), grid.y = 2 directions
    lstm_scan_kernel<<<dim3(64, 2), 512>>>(Whh_f, Whh_b);
    cls_kernel<<<1, 256>>>(W_cls, b_cls, out);
}